// round 14
// baseline (speedup 1.0000x reference)
#include <cuda_runtime.h>
#include <cuda_bf16.h>
#include <math.h>
#include <stdint.h>

// ---------------- problem constants ----------------
#define BB 4
#define SS 2048
#define DD 1024
#define HH 16
#define HDIM 64
#define EE 8
#define HID 4096
#define TOPK 2
#define TT (BB*SS)          // 8192 tokens
#define NE (TT*TOPK)        // 16384 expert entries

typedef unsigned long long u64t;

// ---------------- f32x2 packed-math helpers ---------------------------------
__device__ __forceinline__ u64t pack2(float lo, float hi) {
    u64t r; asm("mov.b64 %0, {%1, %2};" : "=l"(r) : "f"(lo), "f"(hi)); return r;
}
__device__ __forceinline__ void unpack2(float& lo, float& hi, u64t v) {
    asm("mov.b64 {%0, %1}, %2;" : "=f"(lo), "=f"(hi) : "l"(v));
}
__device__ __forceinline__ void fma2(u64t& d, u64t a, u64t b) {
    asm("fma.rn.f32x2 %0, %1, %2, %0;" : "+l"(d) : "l"(a), "l"(b));
}
__device__ __forceinline__ u64t mul2(u64t a, u64t b) {
    u64t r; asm("mul.rn.f32x2 %0, %1, %2;" : "=l"(r) : "l"(a), "l"(b)); return r;
}
__device__ __forceinline__ u64t add2(u64t a, u64t b) {
    u64t r; asm("add.rn.f32x2 %0, %1, %2;" : "=l"(r) : "l"(a), "l"(b)); return r;
}

// ---------------- scratch (device globals; no allocations) ----------------
__device__ float g_q[(size_t)TT*DD];
__device__ float g_k[(size_t)TT*DD];
__device__ float g_v[(size_t)TT*DD];
__device__ float g_att[(size_t)TT*DD];
__device__ float g_tmp[(size_t)TT*DD];
__device__ float g_x1[(size_t)TT*DD];
__device__ float g_x2[(size_t)TT*DD];
__device__ float g_hid[(size_t)NE*HID];   // 256 MiB
__device__ float g_y[(size_t)NE*DD];      // 64 MiB

__device__ int   g_cnt[EE];
__device__ int   g_base[EE];
__device__ int   g_cur[EE];
__device__ int   g_tok[NE];        // entry -> token id
__device__ int   g_te[TT*TOPK];    // token,k -> expert
__device__ float g_tw[TT*TOPK];    // token,k -> gate weight
__device__ int   g_epos[TT*TOPK];  // token,k -> entry position

// ============================================================================
// Dense SGEMM (f32x2, BK=16): C[M,N] = A[M,K] @ B[K,N] + bias
// ============================================================================
#define BM 128
#define BN 128
#define BK 16
#define TM 8
#define TN 8

__global__ __launch_bounds__(256, 2)
void sgemm(const float* __restrict__ A, const float* __restrict__ Bm,
           const float* __restrict__ bias, float* __restrict__ C,
           int M, int N, int Kd, int relu)
{
    int m0 = blockIdx.y * BM, n0 = blockIdx.x * BN;
    __shared__ __align__(16) float As[2][BK][BM];
    __shared__ __align__(16) float Bs[2][BK][BN];
    int tid = threadIdx.x;
    int tx = tid & 15, ty = tid >> 4;

    int arow[2], akc[2], brow[2], bcol[2];
#pragma unroll
    for (int i = 0; i < 2; i++) {
        int c = tid + i * 256;
        arow[i] = c >> 2;  akc[i]  = (c & 3) * 4;
        brow[i] = c >> 5;  bcol[i] = (c & 31) * 4;
    }

    u64t acc2[TM][TN/2];
#pragma unroll
    for (int i = 0; i < TM; i++)
#pragma unroll
        for (int j = 0; j < TN/2; j++) acc2[i][j] = 0ull;

    const float* arp[2];
#pragma unroll
    for (int i = 0; i < 2; i++)
        arp[i] = A + (size_t)(m0 + arow[i]) * Kd + akc[i];

    // prologue: tile 0
#pragma unroll
    for (int i = 0; i < 2; i++) {
        float4 fa = *(const float4*)(arp[i]);
        As[0][akc[i]+0][arow[i]]=fa.x; As[0][akc[i]+1][arow[i]]=fa.y;
        As[0][akc[i]+2][arow[i]]=fa.z; As[0][akc[i]+3][arow[i]]=fa.w;
        float4 fb = *(const float4*)(Bm + (size_t)brow[i] * N + n0 + bcol[i]);
        *(float4*)&Bs[0][brow[i]][bcol[i]] = fb;
    }
    __syncthreads();

    int nk = Kd / BK;
    for (int t = 0; t < nk; t++) {
        int cur = t & 1, nxt = cur ^ 1;
        float4 ra[2], rb[2];
        bool more = (t + 1) < nk;
        if (more) {
            int k0 = (t + 1) * BK;
#pragma unroll
            for (int i = 0; i < 2; i++) {
                ra[i] = *(const float4*)(arp[i] + k0);
                rb[i] = *(const float4*)(Bm + (size_t)(k0 + brow[i]) * N + n0 + bcol[i]);
            }
        }
#pragma unroll
        for (int k = 0; k < BK; k++) {
            const float* as = &As[cur][k][ty*TM];
            float4 a0 = *(const float4*)(as);
            float4 a1 = *(const float4*)(as + 4);
            u64t a2[TM];
            a2[0]=pack2(a0.x,a0.x); a2[1]=pack2(a0.y,a0.y);
            a2[2]=pack2(a0.z,a0.z); a2[3]=pack2(a0.w,a0.w);
            a2[4]=pack2(a1.x,a1.x); a2[5]=pack2(a1.y,a1.y);
            a2[6]=pack2(a1.z,a1.z); a2[7]=pack2(a1.w,a1.w);
            const ulonglong2* bs = (const ulonglong2*)&Bs[cur][k][tx*TN];
            ulonglong2 b01 = bs[0], b23 = bs[1];
            u64t b2[4] = { b01.x, b01.y, b23.x, b23.y };
#pragma unroll
            for (int i = 0; i < TM; i++)
#pragma unroll
                for (int j = 0; j < TN/2; j++)
                    fma2(acc2[i][j], a2[i], b2[j]);
        }
        if (more) {
#pragma unroll
            for (int i = 0; i < 2; i++) {
                As[nxt][akc[i]+0][arow[i]]=ra[i].x; As[nxt][akc[i]+1][arow[i]]=ra[i].y;
                As[nxt][akc[i]+2][arow[i]]=ra[i].z; As[nxt][akc[i]+3][arow[i]]=ra[i].w;
                *(float4*)&Bs[nxt][brow[i]][bcol[i]] = rb[i];
            }
        }
        __syncthreads();
    }
#pragma unroll
    for (int i = 0; i < TM; i++) {
        float* crow = C + (size_t)(m0 + ty*TM + i) * N + n0;
#pragma unroll
        for (int j4 = 0; j4 < TN; j4 += 4) {
            int c = tx*TN + j4;
            float4 v;
            unpack2(v.x, v.y, acc2[i][j4/2]);
            unpack2(v.z, v.w, acc2[i][j4/2 + 1]);
            v.x += bias[n0 + c + 0];
            v.y += bias[n0 + c + 1];
            v.z += bias[n0 + c + 2];
            v.w += bias[n0 + c + 3];
            if (relu) { v.x = fmaxf(v.x,0.f); v.y = fmaxf(v.y,0.f);
                        v.z = fmaxf(v.z,0.f); v.w = fmaxf(v.w,0.f); }
            *(float4*)(crow + c) = v;
        }
    }
}

// ============================================================================
// MoE segmented GEMM (f32x2, BK=16, gathered rows, per-expert weights)
// ============================================================================
template<bool RELU, int GATHER>   // 1: A row = g_tok[entry]; 2: A row = entry
__global__ __launch_bounds__(256, 2)
void moe_gemm(const float* __restrict__ Aall, const float* __restrict__ Ball,
              const float* __restrict__ ball, float* __restrict__ C,
              int N, int Kd)
{
    int e = blockIdx.z;
    int cnt = g_cnt[e], base = g_base[e];
    int m0 = blockIdx.y * BM;
    if (m0 >= cnt) return;
    int n0 = blockIdx.x * BN;
    const float* Bm = Ball + (size_t)e * Kd * N;
    const float* bias = ball + (size_t)e * N;

    __shared__ __align__(16) float As[2][BK][BM];
    __shared__ __align__(16) float Bs[2][BK][BN];
    int tid = threadIdx.x;
    int tx = tid & 15, ty = tid >> 4;

    int arow[2], akc[2], brow[2], bcol[2];
    const float* arp[2];
#pragma unroll
    for (int i = 0; i < 2; i++) {
        int c = tid + i * 256;
        arow[i] = c >> 2;  akc[i]  = (c & 3) * 4;
        brow[i] = c >> 5;  bcol[i] = (c & 31) * 4;
        int r = m0 + arow[i];
        if (r > cnt - 1) r = cnt - 1;
        int grow = (GATHER == 1) ? g_tok[base + r] : (base + r);
        arp[i] = Aall + (size_t)grow * Kd + akc[i];
    }

    u64t acc2[TM][TN/2];
#pragma unroll
    for (int i = 0; i < TM; i++)
#pragma unroll
        for (int j = 0; j < TN/2; j++) acc2[i][j] = 0ull;

#pragma unroll
    for (int i = 0; i < 2; i++) {
        float4 fa = *(const float4*)(arp[i]);
        As[0][akc[i]+0][arow[i]]=fa.x; As[0][akc[i]+1][arow[i]]=fa.y;
        As[0][akc[i]+2][arow[i]]=fa.z; As[0][akc[i]+3][arow[i]]=fa.w;
        float4 fb = *(const float4*)(Bm + (size_t)brow[i] * N + n0 + bcol[i]);
        *(float4*)&Bs[0][brow[i]][bcol[i]] = fb;
    }
    __syncthreads();

    int nk = Kd / BK;
    for (int t = 0; t < nk; t++) {
        int cur = t & 1, nxt = cur ^ 1;
        float4 ra[2], rb[2];
        bool more = (t + 1) < nk;
        if (more) {
            int k0 = (t + 1) * BK;
#pragma unroll
            for (int i = 0; i < 2; i++) {
                ra[i] = *(const float4*)(arp[i] + k0);
                rb[i] = *(const float4*)(Bm + (size_t)(k0 + brow[i]) * N + n0 + bcol[i]);
            }
        }
#pragma unroll
        for (int k = 0; k < BK; k++) {
            const float* as = &As[cur][k][ty*TM];
            float4 a0 = *(const float4*)(as);
            float4 a1 = *(const float4*)(as + 4);
            u64t a2[TM];
            a2[0]=pack2(a0.x,a0.x); a2[1]=pack2(a0.y,a0.y);
            a2[2]=pack2(a0.z,a0.z); a2[3]=pack2(a0.w,a0.w);
            a2[4]=pack2(a1.x,a1.x); a2[5]=pack2(a1.y,a1.y);
            a2[6]=pack2(a1.z,a1.z); a2[7]=pack2(a1.w,a1.w);
            const ulonglong2* bs = (const ulonglong2*)&Bs[cur][k][tx*TN];
            ulonglong2 b01 = bs[0], b23 = bs[1];
            u64t b2[4] = { b01.x, b01.y, b23.x, b23.y };
#pragma unroll
            for (int i = 0; i < TM; i++)
#pragma unroll
                for (int j = 0; j < TN/2; j++)
                    fma2(acc2[i][j], a2[i], b2[j]);
        }
        if (more) {
#pragma unroll
            for (int i = 0; i < 2; i++) {
                As[nxt][akc[i]+0][arow[i]]=ra[i].x; As[nxt][akc[i]+1][arow[i]]=ra[i].y;
                As[nxt][akc[i]+2][arow[i]]=ra[i].z; As[nxt][akc[i]+3][arow[i]]=ra[i].w;
                *(float4*)&Bs[nxt][brow[i]][bcol[i]] = rb[i];
            }
        }
        __syncthreads();
    }
#pragma unroll
    for (int i = 0; i < TM; i++) {
        int rr = m0 + ty*TM + i;
        if (rr >= cnt) continue;
        float* crow = C + (size_t)(base + rr) * N + n0;
#pragma unroll
        for (int j4 = 0; j4 < TN; j4 += 4) {
            int c = tx*TN + j4;
            float4 v;
            unpack2(v.x, v.y, acc2[i][j4/2]);
            unpack2(v.z, v.w, acc2[i][j4/2 + 1]);
            v.x += bias[n0 + c + 0];
            v.y += bias[n0 + c + 1];
            v.z += bias[n0 + c + 2];
            v.w += bias[n0 + c + 3];
            if (RELU) { v.x = fmaxf(v.x,0.f); v.y = fmaxf(v.y,0.f);
                        v.z = fmaxf(v.z,0.f); v.w = fmaxf(v.w,0.f); }
            *(float4*)(crow + c) = v;
        }
    }
}

// ============================================================================
// Flash attention (R11-proven 64-thread version, f32x2 packed inner loops)
// ============================================================================
__global__ __launch_bounds__(64)
void attn_kernel(const float* __restrict__ Qm, const float* __restrict__ Km,
                 const float* __restrict__ Vm, float* __restrict__ Om)
{
    int b = blockIdx.z, h = blockIdx.y;
    int tid = threadIdx.x;
    int q = blockIdx.x * 64 + tid;
    __shared__ __align__(16) float Ks[64][64];
    __shared__ __align__(16) float Vs[64][64];
    size_t hoff = (size_t)h * HDIM;
    const float* qp = Qm + ((size_t)b*SS + q) * DD + hoff;

    u64t qr2[32];
#pragma unroll
    for (int d = 0; d < 16; d++) {
        float4 f = *(const float4*)(qp + d*4);
        qr2[2*d]   = pack2(f.x*0.125f, f.y*0.125f);
        qr2[2*d+1] = pack2(f.z*0.125f, f.w*0.125f);
    }
    u64t o2[32];
#pragma unroll
    for (int d = 0; d < 32; d++) o2[d] = 0ull;
    float m = -1e30f, l = 0.f;

    int lrow = tid >> 4;
    int lcol = (tid & 15) * 4;

    for (int kt = 0; kt < SS; kt += 64) {
        const float* kb = Km + ((size_t)b*SS + kt) * DD + hoff;
        const float* vb = Vm + ((size_t)b*SS + kt) * DD + hoff;
#pragma unroll
        for (int r = 0; r < 64; r += 4) {
            *(float4*)&Ks[r+lrow][lcol] = *(const float4*)(kb + (size_t)(r+lrow)*DD + lcol);
            *(float4*)&Vs[r+lrow][lcol] = *(const float4*)(vb + (size_t)(r+lrow)*DD + lcol);
        }
        __syncthreads();

#pragma unroll 1
        for (int j0 = 0; j0 < 64; j0 += 32) {
            float s[32];
#pragma unroll 4
            for (int j = 0; j < 32; j++) {
                u64t acc0 = 0ull, acc1 = 0ull;
                const ulonglong2* kr = (const ulonglong2*)&Ks[j0+j][0];
#pragma unroll
                for (int d = 0; d < 16; d++) {
                    ulonglong2 kv = kr[d];
                    fma2(acc0, qr2[2*d],   kv.x);
                    fma2(acc1, qr2[2*d+1], kv.y);
                }
                float lo, hi;
                unpack2(lo, hi, add2(acc0, acc1));
                s[j] = lo + hi;
            }
            float mn = m;
#pragma unroll
            for (int j = 0; j < 32; j++) mn = fmaxf(mn, s[j]);
            float corr = __expf(m - mn);
            m = mn;
            l *= corr;
            u64t corr2 = pack2(corr, corr);
#pragma unroll
            for (int d = 0; d < 32; d++) o2[d] = mul2(o2[d], corr2);
#pragma unroll 4
            for (int j = 0; j < 32; j++) {
                float p = __expf(s[j] - mn);
                l += p;
                u64t p2 = pack2(p, p);
                const ulonglong2* vr = (const ulonglong2*)&Vs[j0+j][0];
#pragma unroll
                for (int d = 0; d < 16; d++) {
                    ulonglong2 vv = vr[d];
                    fma2(o2[2*d],   p2, vv.x);
                    fma2(o2[2*d+1], p2, vv.y);
                }
            }
        }
        __syncthreads();
    }
    float inv = 1.f / l;
    float* op = Om + ((size_t)b*SS + q) * DD + hoff;
#pragma unroll
    for (int d = 0; d < 16; d++) {
        float4 f;
        unpack2(f.x, f.y, o2[2*d]);
        unpack2(f.z, f.w, o2[2*d+1]);
        f.x *= inv; f.y *= inv; f.z *= inv; f.w *= inv;
        *(float4*)(op + d*4) = f;
    }
}

// ---------------- residual + layernorm ------------------------------------
__global__ __launch_bounds__(256)
void add_ln_kernel(const float* __restrict__ A, const float* __restrict__ R,
                   const float* __restrict__ g, const float* __restrict__ bt,
                   float* __restrict__ out)
{
    __shared__ float sh[16];
    int t = blockIdx.x;
    int d0 = threadIdx.x * 4;
    float4 a = *(const float4*)(A + (size_t)t*DD + d0);
    float4 r = *(const float4*)(R + (size_t)t*DD + d0);
    float4 v = make_float4(a.x+r.x, a.y+r.y, a.z+r.z, a.w+r.w);
    float sm = v.x+v.y+v.z+v.w;
    float sq = v.x*v.x + v.y*v.y + v.z*v.z + v.w*v.w;
#pragma unroll
    for (int o = 16; o; o >>= 1) { sm += __shfl_xor_sync(~0u, sm, o); sq += __shfl_xor_sync(~0u, sq, o); }
    int w = threadIdx.x >> 5;
    if ((threadIdx.x & 31) == 0) { sh[w] = sm; sh[8+w] = sq; }
    __syncthreads();
    if (threadIdx.x < 8) {
        sm = sh[threadIdx.x]; sq = sh[8 + threadIdx.x];
#pragma unroll
        for (int o = 4; o; o >>= 1) { sm += __shfl_xor_sync(0xffu, sm, o); sq += __shfl_xor_sync(0xffu, sq, o); }
        if (threadIdx.x == 0) { sh[0] = sm; sh[8] = sq; }
    }
    __syncthreads();
    float mean = sh[0] * (1.f/DD);
    float var  = sh[8] * (1.f/DD) - mean*mean;
    float rs = rsqrtf(var + 1e-5f);
    float4 gg = *(const float4*)(g + d0);
    float4 bb = *(const float4*)(bt + d0);
    float4 ov;
    ov.x = (v.x-mean)*rs*gg.x + bb.x;
    ov.y = (v.y-mean)*rs*gg.y + bb.y;
    ov.z = (v.z-mean)*rs*gg.z + bb.z;
    ov.w = (v.w-mean)*rs*gg.w + bb.w;
    *(float4*)(out + (size_t)t*DD + d0) = ov;
}

// ---------------- MoE combine + final layernorm ---------------------------
__global__ __launch_bounds__(256)
void combine_ln_kernel(const float* __restrict__ X, const float* __restrict__ Y,
                       const float* __restrict__ g, const float* __restrict__ bt,
                       float* __restrict__ out)
{
    __shared__ float sh[16];
    int t = blockIdx.x;
    int e0 = g_epos[t*2+0], e1 = g_epos[t*2+1];
    float w0 = g_tw[t*2+0], w1 = g_tw[t*2+1];
    int d0 = threadIdx.x * 4;
    float4 x = *(const float4*)(X + (size_t)t*DD + d0);
    float4 y0 = *(const float4*)(Y + (size_t)e0*DD + d0);
    float4 y1 = *(const float4*)(Y + (size_t)e1*DD + d0);
    float4 v;
    v.x = x.x + w0*y0.x + w1*y1.x;
    v.y = x.y + w0*y0.y + w1*y1.y;
    v.z = x.z + w0*y0.z + w1*y1.z;
    v.w = x.w + w0*y0.w + w1*y1.w;
    float sm = v.x+v.y+v.z+v.w;
    float sq = v.x*v.x + v.y*v.y + v.z*v.z + v.w*v.w;
#pragma unroll
    for (int o = 16; o; o >>= 1) { sm += __shfl_xor_sync(~0u, sm, o); sq += __shfl_xor_sync(~0u, sq, o); }
    int w = threadIdx.x >> 5;
    if ((threadIdx.x & 31) == 0) { sh[w] = sm; sh[8+w] = sq; }
    __syncthreads();
    if (threadIdx.x < 8) {
        sm = sh[threadIdx.x]; sq = sh[8 + threadIdx.x];
#pragma unroll
        for (int o = 4; o; o >>= 1) { sm += __shfl_xor_sync(0xffu, sm, o); sq += __shfl_xor_sync(0xffu, sq, o); }
        if (threadIdx.x == 0) { sh[0] = sm; sh[8] = sq; }
    }
    __syncthreads();
    float mean = sh[0] * (1.f/DD);
    float var  = sh[8] * (1.f/DD) - mean*mean;
    float rs = rsqrtf(var + 1e-5f);
    float4 gg = *(const float4*)(g + d0);
    float4 bb = *(const float4*)(bt + d0);
    float4 ov;
    ov.x = (v.x-mean)*rs*gg.x + bb.x;
    ov.y = (v.y-mean)*rs*gg.y + bb.y;
    ov.z = (v.z-mean)*rs*gg.z + bb.z;
    ov.w = (v.w-mean)*rs*gg.w + bb.w;
    *(float4*)(out + (size_t)t*DD + d0) = ov;
}

// ---------------- router / bookkeeping ------------------------------------
__global__ void zero_cnt_kernel() {
    if (threadIdx.x < EE) g_cnt[threadIdx.x] = 0;
}

__global__ __launch_bounds__(256)
void router_kernel(const float* __restrict__ X, const float* __restrict__ rw,
                   const float* __restrict__ rb)
{
    int warp = (blockIdx.x * blockDim.x + threadIdx.x) >> 5;
    int lane = threadIdx.x & 31;
    if (warp >= TT) return;
    const float* xr = X + (size_t)warp * DD;
    float acc[EE];
#pragma unroll
    for (int e = 0; e < EE; e++) acc[e] = 0.f;
    for (int d = lane; d < DD; d += 32) {
        float xv = xr[d];
        const float* wrow = rw + (size_t)d * EE;
#pragma unroll
        for (int e = 0; e < EE; e++) acc[e] += xv * wrow[e];
    }
#pragma unroll
    for (int e = 0; e < EE; e++)
#pragma unroll
        for (int o = 16; o; o >>= 1) acc[e] += __shfl_xor_sync(~0u, acc[e], o);
    if (lane == 0) {
        float logits[EE], p[EE];
        float mx = -1e30f;
#pragma unroll
        for (int e = 0; e < EE; e++) { logits[e] = acc[e] + rb[e]; mx = fmaxf(mx, logits[e]); }
        float se = 0.f;
#pragma unroll
        for (int e = 0; e < EE; e++) { p[e] = __expf(logits[e] - mx); se += p[e]; }
        float inv = 1.f / se;
#pragma unroll
        for (int e = 0; e < EE; e++) p[e] *= inv;
        int i0 = 0;
#pragma unroll
        for (int e = 1; e < EE; e++) if (p[e] > p[i0]) i0 = e;
        int i1 = (i0 == 0) ? 1 : 0;
#pragma unroll
        for (int e = 0; e < EE; e++) if (e != i0 && p[e] > p[i1]) i1 = e;
        float s = p[i0] + p[i1];
        g_te[warp*2+0] = i0; g_te[warp*2+1] = i1;
        g_tw[warp*2+0] = p[i0] / s; g_tw[warp*2+1] = p[i1] / s;
        atomicAdd(&g_cnt[i0], 1);
        atomicAdd(&g_cnt[i1], 1);
    }
}

__global__ void scan_kernel() {
    if (threadIdx.x == 0) {
        int b = 0;
        for (int e = 0; e < EE; e++) { g_base[e] = b; g_cur[e] = b; b += g_cnt[e]; }
    }
}

__global__ __launch_bounds__(256)
void place_kernel() {
    int t = blockIdx.x * blockDim.x + threadIdx.x;
    if (t >= TT) return;
#pragma unroll
    for (int k = 0; k < TOPK; k++) {
        int e = g_te[t*2+k];
        int pos = atomicAdd(&g_cur[e], 1);
        g_tok[pos] = t;
        g_epos[t*2+k] = pos;
    }
}

// ---------------- launcher -------------------------------------------------
extern "C" void kernel_launch(void* const* d_in, const int* in_sizes, int n_in,
                              void* d_out, int out_size)
{
    const float* tgt   = (const float*)d_in[0];
    const float* mem   = (const float*)d_in[1];
    const float* sa_wq = (const float*)d_in[2];  const float* sa_bq = (const float*)d_in[3];
    const float* sa_wk = (const float*)d_in[4];  const float* sa_bk = (const float*)d_in[5];
    const float* sa_wv = (const float*)d_in[6];  const float* sa_bv = (const float*)d_in[7];
    const float* sa_wo = (const float*)d_in[8];  const float* sa_bo = (const float*)d_in[9];
    const float* ca_wq = (const float*)d_in[10]; const float* ca_bq = (const float*)d_in[11];
    const float* ca_wk = (const float*)d_in[12]; const float* ca_bk = (const float*)d_in[13];
    const float* ca_wv = (const float*)d_in[14]; const float* ca_bv = (const float*)d_in[15];
    const float* ca_wo = (const float*)d_in[16]; const float* ca_bo = (const float*)d_in[17];
    const float* r_w   = (const float*)d_in[18]; const float* r_b   = (const float*)d_in[19];
    const float* e_w1  = (const float*)d_in[20]; const float* e_b1  = (const float*)d_in[21];
    const float* e_w2  = (const float*)d_in[22]; const float* e_b2  = (const float*)d_in[23];
    const float* n1_g  = (const float*)d_in[24]; const float* n1_b  = (const float*)d_in[25];
    const float* n2_g  = (const float*)d_in[26]; const float* n2_b  = (const float*)d_in[27];
    const float* n3_g  = (const float*)d_in[28]; const float* n3_b  = (const float*)d_in[29];
    float* out = (float*)d_out;

    dim3 gproj(DD/BN, TT/BM);        // (8, 64)
    dim3 gattn(SS/64, HH, BB);       // (32, 16, 4)
    dim3 gmoe1(HID/BN, TT/BM, EE);
    dim3 gmoe2(DD/BN,  TT/BM, EE);

    // ---- self-attention block ----
    sgemm<<<gproj, 256>>>(tgt, sa_wq, sa_bq, g_q, TT, DD, DD, 0);
    sgemm<<<gproj, 256>>>(tgt, sa_wk, sa_bk, g_k, TT, DD, DD, 0);
    sgemm<<<gproj, 256>>>(tgt, sa_wv, sa_bv, g_v, TT, DD, DD, 0);
    attn_kernel<<<gattn, 64>>>(g_q, g_k, g_v, g_att);
    sgemm<<<gproj, 256>>>(g_att, sa_wo, sa_bo, g_tmp, TT, DD, DD, 0);
    add_ln_kernel<<<TT, 256>>>(tgt, g_tmp, n1_g, n1_b, g_x1);

    // ---- cross-attention block ----
    sgemm<<<gproj, 256>>>(g_x1, ca_wq, ca_bq, g_q, TT, DD, DD, 0);
    sgemm<<<gproj, 256>>>(mem,  ca_wk, ca_bk, g_k, TT, DD, DD, 0);
    sgemm<<<gproj, 256>>>(mem,  ca_wv, ca_bv, g_v, TT, DD, DD, 0);
    attn_kernel<<<gattn, 64>>>(g_q, g_k, g_v, g_att);
    sgemm<<<gproj, 256>>>(g_att, ca_wo, ca_bo, g_tmp, TT, DD, DD, 0);
    add_ln_kernel<<<TT, 256>>>(g_x1, g_tmp, n2_g, n2_b, g_x2);

    // ---- sparse MoE ----
    zero_cnt_kernel<<<1, 32>>>();
    router_kernel<<<TT/8, 256>>>(g_x2, r_w, r_b);
    scan_kernel<<<1, 32>>>();
    place_kernel<<<TT/256, 256>>>();
    moe_gemm<true,1><<<gmoe1, 256>>>(g_x2,  e_w1, e_b1, g_hid, HID, DD);
    moe_gemm<false,2><<<gmoe2, 256>>>(g_hid, e_w2, e_b2, g_y,  DD,  HID);
    combine_ln_kernel<<<TT, 256>>>(g_x2, g_y, n3_g, n3_b, out);
}

// round 16
// speedup vs baseline: 1.1648x; 1.1648x over previous
#include <cuda_runtime.h>
#include <cuda_bf16.h>
#include <math.h>
#include <stdint.h>

// ---------------- problem constants ----------------
#define BB 4
#define SS 2048
#define DD 1024
#define HH 16
#define HDIM 64
#define EE 8
#define HID 4096
#define TOPK 2
#define TT (BB*SS)          // 8192 tokens
#define NE (TT*TOPK)        // 16384 expert entries

typedef unsigned long long u64t;

// ---------------- f32x2 packed-math helpers ---------------------------------
__device__ __forceinline__ u64t pack2(float lo, float hi) {
    u64t r; asm("mov.b64 %0, {%1, %2};" : "=l"(r) : "f"(lo), "f"(hi)); return r;
}
__device__ __forceinline__ void unpack2(float& lo, float& hi, u64t v) {
    asm("mov.b64 {%0, %1}, %2;" : "=f"(lo), "=f"(hi) : "l"(v));
}
__device__ __forceinline__ void fma2(u64t& d, u64t a, u64t b) {
    asm("fma.rn.f32x2 %0, %1, %2, %0;" : "+l"(d) : "l"(a), "l"(b));
}
__device__ __forceinline__ u64t mul2(u64t a, u64t b) {
    u64t r; asm("mul.rn.f32x2 %0, %1, %2;" : "=l"(r) : "l"(a), "l"(b)); return r;
}
__device__ __forceinline__ u64t add2(u64t a, u64t b) {
    u64t r; asm("add.rn.f32x2 %0, %1, %2;" : "=l"(r) : "l"(a), "l"(b)); return r;
}

// ---------------- scratch (device globals; no allocations) ----------------
__device__ float g_q[(size_t)TT*DD];
__device__ float g_k[(size_t)TT*DD];
__device__ float g_v[(size_t)TT*DD];
__device__ float g_att[(size_t)TT*DD];
__device__ float g_tmp[(size_t)TT*DD];
__device__ float g_x1[(size_t)TT*DD];
__device__ float g_x2[(size_t)TT*DD];
__device__ float g_hid[(size_t)NE*HID];   // 256 MiB
__device__ float g_y[(size_t)NE*DD];      // 64 MiB

__device__ int   g_cnt[EE];
__device__ int   g_base[EE];
__device__ int   g_cur[EE];
__device__ int   g_tok[NE];        // entry -> token id
__device__ int   g_te[TT*TOPK];    // token,k -> expert
__device__ float g_tw[TT*TOPK];    // token,k -> gate weight
__device__ int   g_epos[TT*TOPK];  // token,k -> entry position

// ============================================================================
// Fused projection SGEMM (R11-proven BK=8 body; blockIdx.z selects operands)
// C_z[M,N] = A_z[M,K] @ B_z[K,N] + bias_z
// ============================================================================
#define BM 128
#define BN 128
#define BK 8
#define TM 8
#define TN 8

__global__ __launch_bounds__(256, 2)
void sgemm3(const float* __restrict__ A0, const float* __restrict__ A1, const float* __restrict__ A2,
            const float* __restrict__ B0, const float* __restrict__ B1, const float* __restrict__ B2,
            const float* __restrict__ b0, const float* __restrict__ b1, const float* __restrict__ b2,
            float* __restrict__ C0, float* __restrict__ C1, float* __restrict__ C2,
            int N, int Kd)
{
    int z = blockIdx.z;
    const float* A    = (z == 0) ? A0 : (z == 1) ? A1 : A2;
    const float* Bm   = (z == 0) ? B0 : (z == 1) ? B1 : B2;
    const float* bias = (z == 0) ? b0 : (z == 1) ? b1 : b2;
    float* C          = (z == 0) ? C0 : (z == 1) ? C1 : C2;

    int m0 = blockIdx.y * BM, n0 = blockIdx.x * BN;
    __shared__ __align__(16) float As[2][BK][BM];
    __shared__ __align__(16) float Bs[2][BK][BN];
    int tid = threadIdx.x;
    int arow = tid >> 1;
    int acol = (tid & 1) * 4;
    int brow = tid >> 5;
    int bcol = (tid & 31) * 4;
    int tx = tid & 15, ty = tid >> 4;

    u64t acc2[TM][TN/2];
#pragma unroll
    for (int i = 0; i < TM; i++)
#pragma unroll
        for (int j = 0; j < TN/2; j++) acc2[i][j] = 0ull;

    const float* arp = A + (size_t)(m0 + arow) * Kd;
    {
        float4 fa = *(const float4*)(arp + acol);
        As[0][acol+0][arow]=fa.x; As[0][acol+1][arow]=fa.y;
        As[0][acol+2][arow]=fa.z; As[0][acol+3][arow]=fa.w;
        float4 fb = *(const float4*)(Bm + (size_t)brow * N + n0 + bcol);
        *(float4*)&Bs[0][brow][bcol] = fb;
    }
    __syncthreads();

    int nk = Kd / BK;
    for (int t = 0; t < nk; t++) {
        int cur = t & 1, nxt = cur ^ 1;
        float4 ra, rb;
        bool more = (t + 1) < nk;
        if (more) {
            int k0 = (t + 1) * BK;
            ra = *(const float4*)(arp + k0 + acol);
            rb = *(const float4*)(Bm + (size_t)(k0 + brow) * N + n0 + bcol);
        }
#pragma unroll
        for (int k = 0; k < BK; k++) {
            const float* as = &As[cur][k][ty*TM];
            float4 a0 = *(const float4*)(as);
            float4 a1 = *(const float4*)(as + 4);
            u64t a2[TM];
            a2[0]=pack2(a0.x,a0.x); a2[1]=pack2(a0.y,a0.y);
            a2[2]=pack2(a0.z,a0.z); a2[3]=pack2(a0.w,a0.w);
            a2[4]=pack2(a1.x,a1.x); a2[5]=pack2(a1.y,a1.y);
            a2[6]=pack2(a1.z,a1.z); a2[7]=pack2(a1.w,a1.w);
            const ulonglong2* bs = (const ulonglong2*)&Bs[cur][k][tx*TN];
            ulonglong2 b01 = bs[0], b23 = bs[1];
            u64t b2[4] = { b01.x, b01.y, b23.x, b23.y };
#pragma unroll
            for (int i = 0; i < TM; i++)
#pragma unroll
                for (int j = 0; j < TN/2; j++)
                    fma2(acc2[i][j], a2[i], b2[j]);
        }
        if (more) {
            As[nxt][acol+0][arow]=ra.x; As[nxt][acol+1][arow]=ra.y;
            As[nxt][acol+2][arow]=ra.z; As[nxt][acol+3][arow]=ra.w;
            *(float4*)&Bs[nxt][brow][bcol] = rb;
        }
        __syncthreads();
    }
#pragma unroll
    for (int i = 0; i < TM; i++) {
        float* crow = C + (size_t)(m0 + ty*TM + i) * N + n0;
#pragma unroll
        for (int j4 = 0; j4 < TN; j4 += 4) {
            int c = tx*TN + j4;
            float4 v;
            unpack2(v.x, v.y, acc2[i][j4/2]);
            unpack2(v.z, v.w, acc2[i][j4/2 + 1]);
            v.x += bias[n0 + c + 0];
            v.y += bias[n0 + c + 1];
            v.z += bias[n0 + c + 2];
            v.w += bias[n0 + c + 3];
            *(float4*)(crow + c) = v;
        }
    }
}

// ============================================================================
// Plain dense SGEMM (R11-proven BK=8, single operand set) — O projections
// ============================================================================
__global__ __launch_bounds__(256, 2)
void sgemm(const float* __restrict__ A, const float* __restrict__ Bm,
           const float* __restrict__ bias, float* __restrict__ C,
           int M, int N, int Kd, int relu)
{
    int m0 = blockIdx.y * BM, n0 = blockIdx.x * BN;
    __shared__ __align__(16) float As[2][BK][BM];
    __shared__ __align__(16) float Bs[2][BK][BN];
    int tid = threadIdx.x;
    int arow = tid >> 1;
    int acol = (tid & 1) * 4;
    int brow = tid >> 5;
    int bcol = (tid & 31) * 4;
    int tx = tid & 15, ty = tid >> 4;

    u64t acc2[TM][TN/2];
#pragma unroll
    for (int i = 0; i < TM; i++)
#pragma unroll
        for (int j = 0; j < TN/2; j++) acc2[i][j] = 0ull;

    const float* arp = A + (size_t)(m0 + arow) * Kd;
    {
        float4 fa = *(const float4*)(arp + acol);
        As[0][acol+0][arow]=fa.x; As[0][acol+1][arow]=fa.y;
        As[0][acol+2][arow]=fa.z; As[0][acol+3][arow]=fa.w;
        float4 fb = *(const float4*)(Bm + (size_t)brow * N + n0 + bcol);
        *(float4*)&Bs[0][brow][bcol] = fb;
    }
    __syncthreads();

    int nk = Kd / BK;
    for (int t = 0; t < nk; t++) {
        int cur = t & 1, nxt = cur ^ 1;
        float4 ra, rb;
        bool more = (t + 1) < nk;
        if (more) {
            int k0 = (t + 1) * BK;
            ra = *(const float4*)(arp + k0 + acol);
            rb = *(const float4*)(Bm + (size_t)(k0 + brow) * N + n0 + bcol);
        }
#pragma unroll
        for (int k = 0; k < BK; k++) {
            const float* as = &As[cur][k][ty*TM];
            float4 a0 = *(const float4*)(as);
            float4 a1 = *(const float4*)(as + 4);
            u64t a2[TM];
            a2[0]=pack2(a0.x,a0.x); a2[1]=pack2(a0.y,a0.y);
            a2[2]=pack2(a0.z,a0.z); a2[3]=pack2(a0.w,a0.w);
            a2[4]=pack2(a1.x,a1.x); a2[5]=pack2(a1.y,a1.y);
            a2[6]=pack2(a1.z,a1.z); a2[7]=pack2(a1.w,a1.w);
            const ulonglong2* bs = (const ulonglong2*)&Bs[cur][k][tx*TN];
            ulonglong2 b01 = bs[0], b23 = bs[1];
            u64t b2[4] = { b01.x, b01.y, b23.x, b23.y };
#pragma unroll
            for (int i = 0; i < TM; i++)
#pragma unroll
                for (int j = 0; j < TN/2; j++)
                    fma2(acc2[i][j], a2[i], b2[j]);
        }
        if (more) {
            As[nxt][acol+0][arow]=ra.x; As[nxt][acol+1][arow]=ra.y;
            As[nxt][acol+2][arow]=ra.z; As[nxt][acol+3][arow]=ra.w;
            *(float4*)&Bs[nxt][brow][bcol] = rb;
        }
        __syncthreads();
    }
#pragma unroll
    for (int i = 0; i < TM; i++) {
        float* crow = C + (size_t)(m0 + ty*TM + i) * N + n0;
#pragma unroll
        for (int j4 = 0; j4 < TN; j4 += 4) {
            int c = tx*TN + j4;
            float4 v;
            unpack2(v.x, v.y, acc2[i][j4/2]);
            unpack2(v.z, v.w, acc2[i][j4/2 + 1]);
            v.x += bias[n0 + c + 0];
            v.y += bias[n0 + c + 1];
            v.z += bias[n0 + c + 2];
            v.w += bias[n0 + c + 3];
            if (relu) { v.x = fmaxf(v.x,0.f); v.y = fmaxf(v.y,0.f);
                        v.z = fmaxf(v.z,0.f); v.w = fmaxf(v.w,0.f); }
            *(float4*)(crow + c) = v;
        }
    }
}

// ============================================================================
// MoE segmented GEMM (R11-proven BK=8, f32x2, gathered rows)
// ============================================================================
template<bool RELU, int GATHER>   // 1: A row = g_tok[entry]; 2: A row = entry
__global__ __launch_bounds__(256, 2)
void moe_gemm(const float* __restrict__ Aall, const float* __restrict__ Ball,
              const float* __restrict__ ball, float* __restrict__ C,
              int N, int Kd)
{
    int e = blockIdx.z;
    int cnt = g_cnt[e], base = g_base[e];
    int m0 = blockIdx.y * BM;
    if (m0 >= cnt) return;
    int n0 = blockIdx.x * BN;
    const float* Bm = Ball + (size_t)e * Kd * N;
    const float* bias = ball + (size_t)e * N;

    __shared__ __align__(16) float As[2][BK][BM];
    __shared__ __align__(16) float Bs[2][BK][BN];
    int tid = threadIdx.x;
    int arow = tid >> 1;
    int acol = (tid & 1) * 4;
    int brow = tid >> 5;
    int bcol = (tid & 31) * 4;
    int tx = tid & 15, ty = tid >> 4;

    u64t acc2[TM][TN/2];
#pragma unroll
    for (int i = 0; i < TM; i++)
#pragma unroll
        for (int j = 0; j < TN/2; j++) acc2[i][j] = 0ull;

    int r = m0 + arow;
    if (r > cnt - 1) r = cnt - 1;
    int grow = (GATHER == 1) ? g_tok[base + r] : (base + r);
    const float* arp = Aall + (size_t)grow * Kd;
    {
        float4 fa = *(const float4*)(arp + acol);
        As[0][acol+0][arow]=fa.x; As[0][acol+1][arow]=fa.y;
        As[0][acol+2][arow]=fa.z; As[0][acol+3][arow]=fa.w;
        float4 fb = *(const float4*)(Bm + (size_t)brow * N + n0 + bcol);
        *(float4*)&Bs[0][brow][bcol] = fb;
    }
    __syncthreads();

    int nk = Kd / BK;
    for (int t = 0; t < nk; t++) {
        int cur = t & 1, nxt = cur ^ 1;
        float4 ra, rb;
        bool more = (t + 1) < nk;
        if (more) {
            int k0 = (t + 1) * BK;
            ra = *(const float4*)(arp + k0 + acol);
            rb = *(const float4*)(Bm + (size_t)(k0 + brow) * N + n0 + bcol);
        }
#pragma unroll
        for (int k = 0; k < BK; k++) {
            const float* as = &As[cur][k][ty*TM];
            float4 a0 = *(const float4*)(as);
            float4 a1 = *(const float4*)(as + 4);
            u64t a2[TM];
            a2[0]=pack2(a0.x,a0.x); a2[1]=pack2(a0.y,a0.y);
            a2[2]=pack2(a0.z,a0.z); a2[3]=pack2(a0.w,a0.w);
            a2[4]=pack2(a1.x,a1.x); a2[5]=pack2(a1.y,a1.y);
            a2[6]=pack2(a1.z,a1.z); a2[7]=pack2(a1.w,a1.w);
            const ulonglong2* bs = (const ulonglong2*)&Bs[cur][k][tx*TN];
            ulonglong2 b01 = bs[0], b23 = bs[1];
            u64t b2[4] = { b01.x, b01.y, b23.x, b23.y };
#pragma unroll
            for (int i = 0; i < TM; i++)
#pragma unroll
                for (int j = 0; j < TN/2; j++)
                    fma2(acc2[i][j], a2[i], b2[j]);
        }
        if (more) {
            As[nxt][acol+0][arow]=ra.x; As[nxt][acol+1][arow]=ra.y;
            As[nxt][acol+2][arow]=ra.z; As[nxt][acol+3][arow]=ra.w;
            *(float4*)&Bs[nxt][brow][bcol] = rb;
        }
        __syncthreads();
    }
#pragma unroll
    for (int i = 0; i < TM; i++) {
        int rr = m0 + ty*TM + i;
        if (rr >= cnt) continue;
        float* crow = C + (size_t)(base + rr) * N + n0;
#pragma unroll
        for (int j4 = 0; j4 < TN; j4 += 4) {
            int c = tx*TN + j4;
            float4 v;
            unpack2(v.x, v.y, acc2[i][j4/2]);
            unpack2(v.z, v.w, acc2[i][j4/2 + 1]);
            v.x += bias[n0 + c + 0];
            v.y += bias[n0 + c + 1];
            v.z += bias[n0 + c + 2];
            v.w += bias[n0 + c + 3];
            if (RELU) { v.x = fmaxf(v.x,0.f); v.y = fmaxf(v.y,0.f);
                        v.z = fmaxf(v.z,0.f); v.w = fmaxf(v.w,0.f); }
            *(float4*)(crow + c) = v;
        }
    }
}

// ============================================================================
// Flash attention: 2 threads per query (each owns a 32-dim half).
// 128 threads/block, 64 queries/block; partial dots combined via shfl_xor(16).
// ============================================================================
__global__ __launch_bounds__(128)
void attn_kernel(const float* __restrict__ Qm, const float* __restrict__ Km,
                 const float* __restrict__ Vm, float* __restrict__ Om)
{
    int b = blockIdx.z, h = blockIdx.y;
    int tid = threadIdx.x;
    int lane = tid & 31, warp = tid >> 5;
    int qlocal = warp * 16 + (lane & 15);
    int half = lane >> 4;                 // 0: dims 0-31, 1: dims 32-63
    int q = blockIdx.x * 64 + qlocal;
    __shared__ __align__(16) float Ks[64][64];
    __shared__ __align__(16) float Vs[64][64];
    size_t hoff = (size_t)h * HDIM;
    const float* qp = Qm + ((size_t)b*SS + q) * DD + hoff + half * 32;

    u64t qr2[16];
#pragma unroll
    for (int d = 0; d < 8; d++) {
        float4 f = *(const float4*)(qp + d*4);
        qr2[2*d]   = pack2(f.x*0.125f, f.y*0.125f);
        qr2[2*d+1] = pack2(f.z*0.125f, f.w*0.125f);
    }
    u64t o2[16];
#pragma unroll
    for (int d = 0; d < 16; d++) o2[d] = 0ull;
    float m = -1e30f, l = 0.f;

    int lrow = tid >> 4;            // 0..7
    int lcol = (tid & 15) * 4;      // 0..60

    for (int kt = 0; kt < SS; kt += 64) {
        const float* kb = Km + ((size_t)b*SS + kt) * DD + hoff;
        const float* vb = Vm + ((size_t)b*SS + kt) * DD + hoff;
#pragma unroll
        for (int r = 0; r < 64; r += 8) {
            *(float4*)&Ks[r+lrow][lcol] = *(const float4*)(kb + (size_t)(r+lrow)*DD + lcol);
            *(float4*)&Vs[r+lrow][lcol] = *(const float4*)(vb + (size_t)(r+lrow)*DD + lcol);
        }
        __syncthreads();

#pragma unroll 1
        for (int j0 = 0; j0 < 64; j0 += 32) {
            float s[32];
#pragma unroll 2
            for (int j = 0; j < 32; j++) {
                u64t acc0 = 0ull, acc1 = 0ull;
                const ulonglong2* kr = (const ulonglong2*)&Ks[j0+j][half*32];
#pragma unroll
                for (int d = 0; d < 8; d++) {
                    ulonglong2 kv = kr[d];
                    fma2(acc0, qr2[2*d],   kv.x);
                    fma2(acc1, qr2[2*d+1], kv.y);
                }
                float lo, hi;
                unpack2(lo, hi, add2(acc0, acc1));
                float sh = lo + hi;
                s[j] = sh + __shfl_xor_sync(0xffffffffu, sh, 16);
            }
            float mn = m;
#pragma unroll
            for (int j = 0; j < 32; j++) mn = fmaxf(mn, s[j]);
            float corr = __expf(m - mn);
            m = mn;
            l *= corr;
            u64t corr2 = pack2(corr, corr);
#pragma unroll
            for (int d = 0; d < 16; d++) o2[d] = mul2(o2[d], corr2);
#pragma unroll 2
            for (int j = 0; j < 32; j++) {
                float p = __expf(s[j] - mn);
                l += p;
                u64t p2 = pack2(p, p);
                const ulonglong2* vr = (const ulonglong2*)&Vs[j0+j][half*32];
#pragma unroll
                for (int d = 0; d < 8; d++) {
                    ulonglong2 vv = vr[d];
                    fma2(o2[2*d],   p2, vv.x);
                    fma2(o2[2*d+1], p2, vv.y);
                }
            }
        }
        __syncthreads();
    }
    float inv = 1.f / l;
    float* op = Om + ((size_t)b*SS + q) * DD + hoff + half * 32;
#pragma unroll
    for (int d = 0; d < 8; d++) {
        float4 f;
        unpack2(f.x, f.y, o2[2*d]);
        unpack2(f.z, f.w, o2[2*d+1]);
        f.x *= inv; f.y *= inv; f.z *= inv; f.w *= inv;
        *(float4*)(op + d*4) = f;
    }
}

// ---------------- residual + layernorm ------------------------------------
__global__ __launch_bounds__(256)
void add_ln_kernel(const float* __restrict__ A, const float* __restrict__ R,
                   const float* __restrict__ g, const float* __restrict__ bt,
                   float* __restrict__ out)
{
    __shared__ float sh[16];
    int t = blockIdx.x;
    int d0 = threadIdx.x * 4;
    float4 a = *(const float4*)(A + (size_t)t*DD + d0);
    float4 r = *(const float4*)(R + (size_t)t*DD + d0);
    float4 v = make_float4(a.x+r.x, a.y+r.y, a.z+r.z, a.w+r.w);
    float sm = v.x+v.y+v.z+v.w;
    float sq = v.x*v.x + v.y*v.y + v.z*v.z + v.w*v.w;
#pragma unroll
    for (int o = 16; o; o >>= 1) { sm += __shfl_xor_sync(~0u, sm, o); sq += __shfl_xor_sync(~0u, sq, o); }
    int w = threadIdx.x >> 5;
    if ((threadIdx.x & 31) == 0) { sh[w] = sm; sh[8+w] = sq; }
    __syncthreads();
    if (threadIdx.x < 8) {
        sm = sh[threadIdx.x]; sq = sh[8 + threadIdx.x];
#pragma unroll
        for (int o = 4; o; o >>= 1) { sm += __shfl_xor_sync(0xffu, sm, o); sq += __shfl_xor_sync(0xffu, sq, o); }
        if (threadIdx.x == 0) { sh[0] = sm; sh[8] = sq; }
    }
    __syncthreads();
    float mean = sh[0] * (1.f/DD);
    float var  = sh[8] * (1.f/DD) - mean*mean;
    float rs = rsqrtf(var + 1e-5f);
    float4 gg = *(const float4*)(g + d0);
    float4 bb = *(const float4*)(bt + d0);
    float4 ov;
    ov.x = (v.x-mean)*rs*gg.x + bb.x;
    ov.y = (v.y-mean)*rs*gg.y + bb.y;
    ov.z = (v.z-mean)*rs*gg.z + bb.z;
    ov.w = (v.w-mean)*rs*gg.w + bb.w;
    *(float4*)(out + (size_t)t*DD + d0) = ov;
}

// ---------------- MoE combine + final layernorm ---------------------------
__global__ __launch_bounds__(256)
void combine_ln_kernel(const float* __restrict__ X, const float* __restrict__ Y,
                       const float* __restrict__ g, const float* __restrict__ bt,
                       float* __restrict__ out)
{
    __shared__ float sh[16];
    int t = blockIdx.x;
    int e0 = g_epos[t*2+0], e1 = g_epos[t*2+1];
    float w0 = g_tw[t*2+0], w1 = g_tw[t*2+1];
    int d0 = threadIdx.x * 4;
    float4 x = *(const float4*)(X + (size_t)t*DD + d0);
    float4 y0 = *(const float4*)(Y + (size_t)e0*DD + d0);
    float4 y1 = *(const float4*)(Y + (size_t)e1*DD + d0);
    float4 v;
    v.x = x.x + w0*y0.x + w1*y1.x;
    v.y = x.y + w0*y0.y + w1*y1.y;
    v.z = x.z + w0*y0.z + w1*y1.z;
    v.w = x.w + w0*y0.w + w1*y1.w;
    float sm = v.x+v.y+v.z+v.w;
    float sq = v.x*v.x + v.y*v.y + v.z*v.z + v.w*v.w;
#pragma unroll
    for (int o = 16; o; o >>= 1) { sm += __shfl_xor_sync(~0u, sm, o); sq += __shfl_xor_sync(~0u, sq, o); }
    int w = threadIdx.x >> 5;
    if ((threadIdx.x & 31) == 0) { sh[w] = sm; sh[8+w] = sq; }
    __syncthreads();
    if (threadIdx.x < 8) {
        sm = sh[threadIdx.x]; sq = sh[8 + threadIdx.x];
#pragma unroll
        for (int o = 4; o; o >>= 1) { sm += __shfl_xor_sync(0xffu, sm, o); sq += __shfl_xor_sync(0xffu, sq, o); }
        if (threadIdx.x == 0) { sh[0] = sm; sh[8] = sq; }
    }
    __syncthreads();
    float mean = sh[0] * (1.f/DD);
    float var  = sh[8] * (1.f/DD) - mean*mean;
    float rs = rsqrtf(var + 1e-5f);
    float4 gg = *(const float4*)(g + d0);
    float4 bb = *(const float4*)(bt + d0);
    float4 ov;
    ov.x = (v.x-mean)*rs*gg.x + bb.x;
    ov.y = (v.y-mean)*rs*gg.y + bb.y;
    ov.z = (v.z-mean)*rs*gg.z + bb.z;
    ov.w = (v.w-mean)*rs*gg.w + bb.w;
    *(float4*)(out + (size_t)t*DD + d0) = ov;
}

// ---------------- router / bookkeeping ------------------------------------
__global__ void zero_cnt_kernel() {
    if (threadIdx.x < EE) g_cnt[threadIdx.x] = 0;
}

__global__ __launch_bounds__(256)
void router_kernel(const float* __restrict__ X, const float* __restrict__ rw,
                   const float* __restrict__ rb)
{
    int warp = (blockIdx.x * blockDim.x + threadIdx.x) >> 5;
    int lane = threadIdx.x & 31;
    if (warp >= TT) return;
    const float* xr = X + (size_t)warp * DD;
    float acc[EE];
#pragma unroll
    for (int e = 0; e < EE; e++) acc[e] = 0.f;
    for (int d = lane; d < DD; d += 32) {
        float xv = xr[d];
        const float* wrow = rw + (size_t)d * EE;
#pragma unroll
        for (int e = 0; e < EE; e++) acc[e] += xv * wrow[e];
    }
#pragma unroll
    for (int e = 0; e < EE; e++)
#pragma unroll
        for (int o = 16; o; o >>= 1) acc[e] += __shfl_xor_sync(~0u, acc[e], o);
    if (lane == 0) {
        float logits[EE], p[EE];
        float mx = -1e30f;
#pragma unroll
        for (int e = 0; e < EE; e++) { logits[e] = acc[e] + rb[e]; mx = fmaxf(mx, logits[e]); }
        float se = 0.f;
#pragma unroll
        for (int e = 0; e < EE; e++) { p[e] = __expf(logits[e] - mx); se += p[e]; }
        float inv = 1.f / se;
#pragma unroll
        for (int e = 0; e < EE; e++) p[e] *= inv;
        int i0 = 0;
#pragma unroll
        for (int e = 1; e < EE; e++) if (p[e] > p[i0]) i0 = e;
        int i1 = (i0 == 0) ? 1 : 0;
#pragma unroll
        for (int e = 0; e < EE; e++) if (e != i0 && p[e] > p[i1]) i1 = e;
        float s = p[i0] + p[i1];
        g_te[warp*2+0] = i0; g_te[warp*2+1] = i1;
        g_tw[warp*2+0] = p[i0] / s; g_tw[warp*2+1] = p[i1] / s;
        atomicAdd(&g_cnt[i0], 1);
        atomicAdd(&g_cnt[i1], 1);
    }
}

__global__ void scan_kernel() {
    if (threadIdx.x == 0) {
        int b = 0;
        for (int e = 0; e < EE; e++) { g_base[e] = b; g_cur[e] = b; b += g_cnt[e]; }
    }
}

__global__ __launch_bounds__(256)
void place_kernel() {
    int t = blockIdx.x * blockDim.x + threadIdx.x;
    if (t >= TT) return;
#pragma unroll
    for (int k = 0; k < TOPK; k++) {
        int e = g_te[t*2+k];
        int pos = atomicAdd(&g_cur[e], 1);
        g_tok[pos] = t;
        g_epos[t*2+k] = pos;
    }
}

// ---------------- launcher -------------------------------------------------
extern "C" void kernel_launch(void* const* d_in, const int* in_sizes, int n_in,
                              void* d_out, int out_size)
{
    const float* tgt   = (const float*)d_in[0];
    const float* mem   = (const float*)d_in[1];
    const float* sa_wq = (const float*)d_in[2];  const float* sa_bq = (const float*)d_in[3];
    const float* sa_wk = (const float*)d_in[4];  const float* sa_bk = (const float*)d_in[5];
    const float* sa_wv = (const float*)d_in[6];  const float* sa_bv = (const float*)d_in[7];
    const float* sa_wo = (const float*)d_in[8];  const float* sa_bo = (const float*)d_in[9];
    const float* ca_wq = (const float*)d_in[10]; const float* ca_bq = (const float*)d_in[11];
    const float* ca_wk = (const float*)d_in[12]; const float* ca_bk = (const float*)d_in[13];
    const float* ca_wv = (const float*)d_in[14]; const float* ca_bv = (const float*)d_in[15];
    const float* ca_wo = (const float*)d_in[16]; const float* ca_bo = (const float*)d_in[17];
    const float* r_w   = (const float*)d_in[18]; const float* r_b   = (const float*)d_in[19];
    const float* e_w1  = (const float*)d_in[20]; const float* e_b1  = (const float*)d_in[21];
    const float* e_w2  = (const float*)d_in[22]; const float* e_b2  = (const float*)d_in[23];
    const float* n1_g  = (const float*)d_in[24]; const float* n1_b  = (const float*)d_in[25];
    const float* n2_g  = (const float*)d_in[26]; const float* n2_b  = (const float*)d_in[27];
    const float* n3_g  = (const float*)d_in[28]; const float* n3_b  = (const float*)d_in[29];
    float* out = (float*)d_out;

    dim3 gproj(DD/BN, TT/BM);          // (8, 64)
    dim3 gproj3(DD/BN, TT/BM, 3);      // fused QKV
    dim3 gattn(SS/64, HH, BB);         // (32, 16, 4)
    dim3 gmoe1(HID/BN, TT/BM, EE);
    dim3 gmoe2(DD/BN,  TT/BM, EE);

    // ---- self-attention block (fused QKV projection) ----
    sgemm3<<<gproj3, 256>>>(tgt, tgt, tgt,
                            sa_wq, sa_wk, sa_wv,
                            sa_bq, sa_bk, sa_bv,
                            g_q, g_k, g_v, DD, DD);
    attn_kernel<<<gattn, 128>>>(g_q, g_k, g_v, g_att);
    sgemm<<<gproj, 256>>>(g_att, sa_wo, sa_bo, g_tmp, TT, DD, DD, 0);
    add_ln_kernel<<<TT, 256>>>(tgt, g_tmp, n1_g, n1_b, g_x1);

    // ---- cross-attention block (fused Q|K|V projection) ----
    sgemm3<<<gproj3, 256>>>(g_x1, mem, mem,
                            ca_wq, ca_wk, ca_wv,
                            ca_bq, ca_bk, ca_bv,
                            g_q, g_k, g_v, DD, DD);
    attn_kernel<<<gattn, 128>>>(g_q, g_k, g_v, g_att);
    sgemm<<<gproj, 256>>>(g_att, ca_wo, ca_bo, g_tmp, TT, DD, DD, 0);
    add_ln_kernel<<<TT, 256>>>(g_x1, g_tmp, n2_g, n2_b, g_x2);

    // ---- sparse MoE ----
    zero_cnt_kernel<<<1, 32>>>();
    router_kernel<<<TT/8, 256>>>(g_x2, r_w, r_b);
    scan_kernel<<<1, 32>>>();
    place_kernel<<<TT/256, 256>>>();
    moe_gemm<true,1><<<gmoe1, 256>>>(g_x2,  e_w1, e_b1, g_hid, HID, DD);
    moe_gemm<false,2><<<gmoe2, 256>>>(g_hid, e_w2, e_b2, g_y,  DD,  HID);
    combine_ln_kernel<<<TT, 256>>>(g_x2, g_y, n3_g, n3_b, out);
}

// round 17
// speedup vs baseline: 1.2118x; 1.0404x over previous
#include <cuda_runtime.h>
#include <cuda_bf16.h>
#include <math.h>
#include <stdint.h>

// ---------------- problem constants ----------------
#define BB 4
#define SS 2048
#define DD 1024
#define HH 16
#define HDIM 64
#define EE 8
#define HID 4096
#define TOPK 2
#define TT (BB*SS)          // 8192 tokens
#define NE (TT*TOPK)        // 16384 expert entries

typedef unsigned long long u64t;

// ---------------- f32x2 packed-math helpers ---------------------------------
__device__ __forceinline__ u64t pack2(float lo, float hi) {
    u64t r; asm("mov.b64 %0, {%1, %2};" : "=l"(r) : "f"(lo), "f"(hi)); return r;
}
__device__ __forceinline__ void unpack2(float& lo, float& hi, u64t v) {
    asm("mov.b64 {%0, %1}, %2;" : "=f"(lo), "=f"(hi) : "l"(v));
}
__device__ __forceinline__ void fma2(u64t& d, u64t a, u64t b) {
    asm("fma.rn.f32x2 %0, %1, %2, %0;" : "+l"(d) : "l"(a), "l"(b));
}
__device__ __forceinline__ u64t mul2(u64t a, u64t b) {
    u64t r; asm("mul.rn.f32x2 %0, %1, %2;" : "=l"(r) : "l"(a), "l"(b)); return r;
}
__device__ __forceinline__ u64t add2(u64t a, u64t b) {
    u64t r; asm("add.rn.f32x2 %0, %1, %2;" : "=l"(r) : "l"(a), "l"(b)); return r;
}

// ---------------- scratch (device globals; no allocations) ----------------
__device__ float g_q[(size_t)TT*DD];
__device__ float g_k[(size_t)TT*DD];
__device__ float g_v[(size_t)TT*DD];
__device__ float g_att[(size_t)TT*DD];
__device__ float g_tmp[(size_t)TT*DD];
__device__ float g_x1[(size_t)TT*DD];
__device__ float g_x2[(size_t)TT*DD];
__device__ float g_hid[(size_t)NE*HID];   // 256 MiB
__device__ float g_y[(size_t)NE*DD];      // 64 MiB

__device__ int   g_cnt[EE];
__device__ int   g_base[EE];
__device__ int   g_cur[EE];
__device__ int   g_tok[NE];        // entry -> token id
__device__ int   g_te[TT*TOPK];    // token,k -> expert
__device__ float g_tw[TT*TOPK];    // token,k -> gate weight
__device__ int   g_epos[TT*TOPK];  // token,k -> entry position

// ============================================================================
// Fused projection SGEMM (R11-proven BK=8 body; blockIdx.z selects operands)
// ============================================================================
#define BM 128
#define BN 128
#define BK 8
#define TM 8
#define TN 8

__global__ __launch_bounds__(256, 2)
void sgemm3(const float* __restrict__ A0, const float* __restrict__ A1, const float* __restrict__ A2,
            const float* __restrict__ B0, const float* __restrict__ B1, const float* __restrict__ B2,
            const float* __restrict__ b0, const float* __restrict__ b1, const float* __restrict__ b2,
            float* __restrict__ C0, float* __restrict__ C1, float* __restrict__ C2,
            int N, int Kd)
{
    int z = blockIdx.z;
    const float* A    = (z == 0) ? A0 : (z == 1) ? A1 : A2;
    const float* Bm   = (z == 0) ? B0 : (z == 1) ? B1 : B2;
    const float* bias = (z == 0) ? b0 : (z == 1) ? b1 : b2;
    float* C          = (z == 0) ? C0 : (z == 1) ? C1 : C2;

    int m0 = blockIdx.y * BM, n0 = blockIdx.x * BN;
    __shared__ __align__(16) float As[2][BK][BM];
    __shared__ __align__(16) float Bs[2][BK][BN];
    int tid = threadIdx.x;
    int arow = tid >> 1;
    int acol = (tid & 1) * 4;
    int brow = tid >> 5;
    int bcol = (tid & 31) * 4;
    int tx = tid & 15, ty = tid >> 4;

    u64t acc2[TM][TN/2];
#pragma unroll
    for (int i = 0; i < TM; i++)
#pragma unroll
        for (int j = 0; j < TN/2; j++) acc2[i][j] = 0ull;

    const float* arp = A + (size_t)(m0 + arow) * Kd;
    {
        float4 fa = *(const float4*)(arp + acol);
        As[0][acol+0][arow]=fa.x; As[0][acol+1][arow]=fa.y;
        As[0][acol+2][arow]=fa.z; As[0][acol+3][arow]=fa.w;
        float4 fb = *(const float4*)(Bm + (size_t)brow * N + n0 + bcol);
        *(float4*)&Bs[0][brow][bcol] = fb;
    }
    __syncthreads();

    int nk = Kd / BK;
    for (int t = 0; t < nk; t++) {
        int cur = t & 1, nxt = cur ^ 1;
        float4 ra, rb;
        bool more = (t + 1) < nk;
        if (more) {
            int k0 = (t + 1) * BK;
            ra = *(const float4*)(arp + k0 + acol);
            rb = *(const float4*)(Bm + (size_t)(k0 + brow) * N + n0 + bcol);
        }
#pragma unroll
        for (int k = 0; k < BK; k++) {
            const float* as = &As[cur][k][ty*TM];
            float4 a0 = *(const float4*)(as);
            float4 a1 = *(const float4*)(as + 4);
            u64t a2[TM];
            a2[0]=pack2(a0.x,a0.x); a2[1]=pack2(a0.y,a0.y);
            a2[2]=pack2(a0.z,a0.z); a2[3]=pack2(a0.w,a0.w);
            a2[4]=pack2(a1.x,a1.x); a2[5]=pack2(a1.y,a1.y);
            a2[6]=pack2(a1.z,a1.z); a2[7]=pack2(a1.w,a1.w);
            const ulonglong2* bs = (const ulonglong2*)&Bs[cur][k][tx*TN];
            ulonglong2 b01 = bs[0], b23 = bs[1];
            u64t b2[4] = { b01.x, b01.y, b23.x, b23.y };
#pragma unroll
            for (int i = 0; i < TM; i++)
#pragma unroll
                for (int j = 0; j < TN/2; j++)
                    fma2(acc2[i][j], a2[i], b2[j]);
        }
        if (more) {
            As[nxt][acol+0][arow]=ra.x; As[nxt][acol+1][arow]=ra.y;
            As[nxt][acol+2][arow]=ra.z; As[nxt][acol+3][arow]=ra.w;
            *(float4*)&Bs[nxt][brow][bcol] = rb;
        }
        __syncthreads();
    }
#pragma unroll
    for (int i = 0; i < TM; i++) {
        float* crow = C + (size_t)(m0 + ty*TM + i) * N + n0;
#pragma unroll
        for (int j4 = 0; j4 < TN; j4 += 4) {
            int c = tx*TN + j4;
            float4 v;
            unpack2(v.x, v.y, acc2[i][j4/2]);
            unpack2(v.z, v.w, acc2[i][j4/2 + 1]);
            v.x += bias[n0 + c + 0];
            v.y += bias[n0 + c + 1];
            v.z += bias[n0 + c + 2];
            v.w += bias[n0 + c + 3];
            *(float4*)(crow + c) = v;
        }
    }
}

// ============================================================================
// Dense SGEMM (R11 BK=8 body) with optional fused residual add in epilogue:
// RESID=1: C[row] = acc + bias + R[row]   (for O-projection + residual)
// ============================================================================
template<int RESID>
__global__ __launch_bounds__(256, 2)
void sgemm_r(const float* __restrict__ A, const float* __restrict__ Bm,
             const float* __restrict__ bias, const float* __restrict__ R,
             float* __restrict__ C, int N, int Kd)
{
    int m0 = blockIdx.y * BM, n0 = blockIdx.x * BN;
    __shared__ __align__(16) float As[2][BK][BM];
    __shared__ __align__(16) float Bs[2][BK][BN];
    int tid = threadIdx.x;
    int arow = tid >> 1;
    int acol = (tid & 1) * 4;
    int brow = tid >> 5;
    int bcol = (tid & 31) * 4;
    int tx = tid & 15, ty = tid >> 4;

    u64t acc2[TM][TN/2];
#pragma unroll
    for (int i = 0; i < TM; i++)
#pragma unroll
        for (int j = 0; j < TN/2; j++) acc2[i][j] = 0ull;

    const float* arp = A + (size_t)(m0 + arow) * Kd;
    {
        float4 fa = *(const float4*)(arp + acol);
        As[0][acol+0][arow]=fa.x; As[0][acol+1][arow]=fa.y;
        As[0][acol+2][arow]=fa.z; As[0][acol+3][arow]=fa.w;
        float4 fb = *(const float4*)(Bm + (size_t)brow * N + n0 + bcol);
        *(float4*)&Bs[0][brow][bcol] = fb;
    }
    __syncthreads();

    int nk = Kd / BK;
    for (int t = 0; t < nk; t++) {
        int cur = t & 1, nxt = cur ^ 1;
        float4 ra, rb;
        bool more = (t + 1) < nk;
        if (more) {
            int k0 = (t + 1) * BK;
            ra = *(const float4*)(arp + k0 + acol);
            rb = *(const float4*)(Bm + (size_t)(k0 + brow) * N + n0 + bcol);
        }
#pragma unroll
        for (int k = 0; k < BK; k++) {
            const float* as = &As[cur][k][ty*TM];
            float4 a0 = *(const float4*)(as);
            float4 a1 = *(const float4*)(as + 4);
            u64t a2[TM];
            a2[0]=pack2(a0.x,a0.x); a2[1]=pack2(a0.y,a0.y);
            a2[2]=pack2(a0.z,a0.z); a2[3]=pack2(a0.w,a0.w);
            a2[4]=pack2(a1.x,a1.x); a2[5]=pack2(a1.y,a1.y);
            a2[6]=pack2(a1.z,a1.z); a2[7]=pack2(a1.w,a1.w);
            const ulonglong2* bs = (const ulonglong2*)&Bs[cur][k][tx*TN];
            ulonglong2 b01 = bs[0], b23 = bs[1];
            u64t b2[4] = { b01.x, b01.y, b23.x, b23.y };
#pragma unroll
            for (int i = 0; i < TM; i++)
#pragma unroll
                for (int j = 0; j < TN/2; j++)
                    fma2(acc2[i][j], a2[i], b2[j]);
        }
        if (more) {
            As[nxt][acol+0][arow]=ra.x; As[nxt][acol+1][arow]=ra.y;
            As[nxt][acol+2][arow]=ra.z; As[nxt][acol+3][arow]=ra.w;
            *(float4*)&Bs[nxt][brow][bcol] = rb;
        }
        __syncthreads();
    }
#pragma unroll
    for (int i = 0; i < TM; i++) {
        size_t roff = (size_t)(m0 + ty*TM + i) * N + n0;
        float* crow = C + roff;
        const float* rrow = R + roff;
#pragma unroll
        for (int j4 = 0; j4 < TN; j4 += 4) {
            int c = tx*TN + j4;
            float4 v;
            unpack2(v.x, v.y, acc2[i][j4/2]);
            unpack2(v.z, v.w, acc2[i][j4/2 + 1]);
            v.x += bias[n0 + c + 0];
            v.y += bias[n0 + c + 1];
            v.z += bias[n0 + c + 2];
            v.w += bias[n0 + c + 3];
            if (RESID) {
                float4 rr = *(const float4*)(rrow + c);
                v.x += rr.x; v.y += rr.y; v.z += rr.z; v.w += rr.w;
            }
            *(float4*)(crow + c) = v;
        }
    }
}

// ============================================================================
// MoE segmented GEMM (R11-proven BK=8, f32x2, gathered rows)
// ============================================================================
template<bool RELU, int GATHER>   // 1: A row = g_tok[entry]; 2: A row = entry
__global__ __launch_bounds__(256, 2)
void moe_gemm(const float* __restrict__ Aall, const float* __restrict__ Ball,
              const float* __restrict__ ball, float* __restrict__ C,
              int N, int Kd)
{
    int e = blockIdx.z;
    int cnt = g_cnt[e], base = g_base[e];
    int m0 = blockIdx.y * BM;
    if (m0 >= cnt) return;
    int n0 = blockIdx.x * BN;
    const float* Bm = Ball + (size_t)e * Kd * N;
    const float* bias = ball + (size_t)e * N;

    __shared__ __align__(16) float As[2][BK][BM];
    __shared__ __align__(16) float Bs[2][BK][BN];
    int tid = threadIdx.x;
    int arow = tid >> 1;
    int acol = (tid & 1) * 4;
    int brow = tid >> 5;
    int bcol = (tid & 31) * 4;
    int tx = tid & 15, ty = tid >> 4;

    u64t acc2[TM][TN/2];
#pragma unroll
    for (int i = 0; i < TM; i++)
#pragma unroll
        for (int j = 0; j < TN/2; j++) acc2[i][j] = 0ull;

    int r = m0 + arow;
    if (r > cnt - 1) r = cnt - 1;
    int grow = (GATHER == 1) ? g_tok[base + r] : (base + r);
    const float* arp = Aall + (size_t)grow * Kd;
    {
        float4 fa = *(const float4*)(arp + acol);
        As[0][acol+0][arow]=fa.x; As[0][acol+1][arow]=fa.y;
        As[0][acol+2][arow]=fa.z; As[0][acol+3][arow]=fa.w;
        float4 fb = *(const float4*)(Bm + (size_t)brow * N + n0 + bcol);
        *(float4*)&Bs[0][brow][bcol] = fb;
    }
    __syncthreads();

    int nk = Kd / BK;
    for (int t = 0; t < nk; t++) {
        int cur = t & 1, nxt = cur ^ 1;
        float4 ra, rb;
        bool more = (t + 1) < nk;
        if (more) {
            int k0 = (t + 1) * BK;
            ra = *(const float4*)(arp + k0 + acol);
            rb = *(const float4*)(Bm + (size_t)(k0 + brow) * N + n0 + bcol);
        }
#pragma unroll
        for (int k = 0; k < BK; k++) {
            const float* as = &As[cur][k][ty*TM];
            float4 a0 = *(const float4*)(as);
            float4 a1 = *(const float4*)(as + 4);
            u64t a2[TM];
            a2[0]=pack2(a0.x,a0.x); a2[1]=pack2(a0.y,a0.y);
            a2[2]=pack2(a0.z,a0.z); a2[3]=pack2(a0.w,a0.w);
            a2[4]=pack2(a1.x,a1.x); a2[5]=pack2(a1.y,a1.y);
            a2[6]=pack2(a1.z,a1.z); a2[7]=pack2(a1.w,a1.w);
            const ulonglong2* bs = (const ulonglong2*)&Bs[cur][k][tx*TN];
            ulonglong2 b01 = bs[0], b23 = bs[1];
            u64t b2[4] = { b01.x, b01.y, b23.x, b23.y };
#pragma unroll
            for (int i = 0; i < TM; i++)
#pragma unroll
                for (int j = 0; j < TN/2; j++)
                    fma2(acc2[i][j], a2[i], b2[j]);
        }
        if (more) {
            As[nxt][acol+0][arow]=ra.x; As[nxt][acol+1][arow]=ra.y;
            As[nxt][acol+2][arow]=ra.z; As[nxt][acol+3][arow]=ra.w;
            *(float4*)&Bs[nxt][brow][bcol] = rb;
        }
        __syncthreads();
    }
#pragma unroll
    for (int i = 0; i < TM; i++) {
        int rr = m0 + ty*TM + i;
        if (rr >= cnt) continue;
        float* crow = C + (size_t)(base + rr) * N + n0;
#pragma unroll
        for (int j4 = 0; j4 < TN; j4 += 4) {
            int c = tx*TN + j4;
            float4 v;
            unpack2(v.x, v.y, acc2[i][j4/2]);
            unpack2(v.z, v.w, acc2[i][j4/2 + 1]);
            v.x += bias[n0 + c + 0];
            v.y += bias[n0 + c + 1];
            v.z += bias[n0 + c + 2];
            v.w += bias[n0 + c + 3];
            if (RELU) { v.x = fmaxf(v.x,0.f); v.y = fmaxf(v.y,0.f);
                        v.z = fmaxf(v.z,0.f); v.w = fmaxf(v.w,0.f); }
            *(float4*)(crow + c) = v;
        }
    }
}

// ============================================================================
// Flash attention (R11-proven 64-thread version, f32x2 packed inner loops)
// ============================================================================
__global__ __launch_bounds__(64)
void attn_kernel(const float* __restrict__ Qm, const float* __restrict__ Km,
                 const float* __restrict__ Vm, float* __restrict__ Om)
{
    int b = blockIdx.z, h = blockIdx.y;
    int tid = threadIdx.x;
    int q = blockIdx.x * 64 + tid;
    __shared__ __align__(16) float Ks[64][64];
    __shared__ __align__(16) float Vs[64][64];
    size_t hoff = (size_t)h * HDIM;
    const float* qp = Qm + ((size_t)b*SS + q) * DD + hoff;

    u64t qr2[32];
#pragma unroll
    for (int d = 0; d < 16; d++) {
        float4 f = *(const float4*)(qp + d*4);
        qr2[2*d]   = pack2(f.x*0.125f, f.y*0.125f);
        qr2[2*d+1] = pack2(f.z*0.125f, f.w*0.125f);
    }
    u64t o2[32];
#pragma unroll
    for (int d = 0; d < 32; d++) o2[d] = 0ull;
    float m = -1e30f, l = 0.f;

    int lrow = tid >> 4;
    int lcol = (tid & 15) * 4;

    for (int kt = 0; kt < SS; kt += 64) {
        const float* kb = Km + ((size_t)b*SS + kt) * DD + hoff;
        const float* vb = Vm + ((size_t)b*SS + kt) * DD + hoff;
#pragma unroll
        for (int r = 0; r < 64; r += 4) {
            *(float4*)&Ks[r+lrow][lcol] = *(const float4*)(kb + (size_t)(r+lrow)*DD + lcol);
            *(float4*)&Vs[r+lrow][lcol] = *(const float4*)(vb + (size_t)(r+lrow)*DD + lcol);
        }
        __syncthreads();

#pragma unroll 1
        for (int j0 = 0; j0 < 64; j0 += 32) {
            float s[32];
#pragma unroll 4
            for (int j = 0; j < 32; j++) {
                u64t acc0 = 0ull, acc1 = 0ull;
                const ulonglong2* kr = (const ulonglong2*)&Ks[j0+j][0];
#pragma unroll
                for (int d = 0; d < 16; d++) {
                    ulonglong2 kv = kr[d];
                    fma2(acc0, qr2[2*d],   kv.x);
                    fma2(acc1, qr2[2*d+1], kv.y);
                }
                float lo, hi;
                unpack2(lo, hi, add2(acc0, acc1));
                s[j] = lo + hi;
            }
            float mn = m;
#pragma unroll
            for (int j = 0; j < 32; j++) mn = fmaxf(mn, s[j]);
            float corr = __expf(m - mn);
            m = mn;
            l *= corr;
            u64t corr2 = pack2(corr, corr);
#pragma unroll
            for (int d = 0; d < 32; d++) o2[d] = mul2(o2[d], corr2);
#pragma unroll 4
            for (int j = 0; j < 32; j++) {
                float p = __expf(s[j] - mn);
                l += p;
                u64t p2 = pack2(p, p);
                const ulonglong2* vr = (const ulonglong2*)&Vs[j0+j][0];
#pragma unroll
                for (int d = 0; d < 16; d++) {
                    ulonglong2 vv = vr[d];
                    fma2(o2[2*d],   p2, vv.x);
                    fma2(o2[2*d+1], p2, vv.y);
                }
            }
        }
        __syncthreads();
    }
    float inv = 1.f / l;
    float* op = Om + ((size_t)b*SS + q) * DD + hoff;
#pragma unroll
    for (int d = 0; d < 16; d++) {
        float4 f;
        unpack2(f.x, f.y, o2[2*d]);
        unpack2(f.z, f.w, o2[2*d+1]);
        f.x *= inv; f.y *= inv; f.z *= inv; f.w *= inv;
        *(float4*)(op + d*4) = f;
    }
}

// ---------------- layernorm (single input; residual pre-folded) ------------
__global__ __launch_bounds__(256)
void ln_kernel(const float* __restrict__ X,
               const float* __restrict__ g, const float* __restrict__ bt,
               float* __restrict__ out)
{
    __shared__ float sh[16];
    int t = blockIdx.x;
    int d0 = threadIdx.x * 4;
    float4 v = *(const float4*)(X + (size_t)t*DD + d0);
    float sm = v.x+v.y+v.z+v.w;
    float sq = v.x*v.x + v.y*v.y + v.z*v.z + v.w*v.w;
#pragma unroll
    for (int o = 16; o; o >>= 1) { sm += __shfl_xor_sync(~0u, sm, o); sq += __shfl_xor_sync(~0u, sq, o); }
    int w = threadIdx.x >> 5;
    if ((threadIdx.x & 31) == 0) { sh[w] = sm; sh[8+w] = sq; }
    __syncthreads();
    if (threadIdx.x < 8) {
        sm = sh[threadIdx.x]; sq = sh[8 + threadIdx.x];
#pragma unroll
        for (int o = 4; o; o >>= 1) { sm += __shfl_xor_sync(0xffu, sm, o); sq += __shfl_xor_sync(0xffu, sq, o); }
        if (threadIdx.x == 0) { sh[0] = sm; sh[8] = sq; }
    }
    __syncthreads();
    float mean = sh[0] * (1.f/DD);
    float var  = sh[8] * (1.f/DD) - mean*mean;
    float rs = rsqrtf(var + 1e-5f);
    float4 gg = *(const float4*)(g + d0);
    float4 bb = *(const float4*)(bt + d0);
    float4 ov;
    ov.x = (v.x-mean)*rs*gg.x + bb.x;
    ov.y = (v.y-mean)*rs*gg.y + bb.y;
    ov.z = (v.z-mean)*rs*gg.z + bb.z;
    ov.w = (v.w-mean)*rs*gg.w + bb.w;
    *(float4*)(out + (size_t)t*DD + d0) = ov;
}

// ---------------- MoE combine + final layernorm ---------------------------
__global__ __launch_bounds__(256)
void combine_ln_kernel(const float* __restrict__ X, const float* __restrict__ Y,
                       const float* __restrict__ g, const float* __restrict__ bt,
                       float* __restrict__ out)
{
    __shared__ float sh[16];
    int t = blockIdx.x;
    int e0 = g_epos[t*2+0], e1 = g_epos[t*2+1];
    float w0 = g_tw[t*2+0], w1 = g_tw[t*2+1];
    int d0 = threadIdx.x * 4;
    float4 x = *(const float4*)(X + (size_t)t*DD + d0);
    float4 y0 = *(const float4*)(Y + (size_t)e0*DD + d0);
    float4 y1 = *(const float4*)(Y + (size_t)e1*DD + d0);
    float4 v;
    v.x = x.x + w0*y0.x + w1*y1.x;
    v.y = x.y + w0*y0.y + w1*y1.y;
    v.z = x.z + w0*y0.z + w1*y1.z;
    v.w = x.w + w0*y0.w + w1*y1.w;
    float sm = v.x+v.y+v.z+v.w;
    float sq = v.x*v.x + v.y*v.y + v.z*v.z + v.w*v.w;
#pragma unroll
    for (int o = 16; o; o >>= 1) { sm += __shfl_xor_sync(~0u, sm, o); sq += __shfl_xor_sync(~0u, sq, o); }
    int w = threadIdx.x >> 5;
    if ((threadIdx.x & 31) == 0) { sh[w] = sm; sh[8+w] = sq; }
    __syncthreads();
    if (threadIdx.x < 8) {
        sm = sh[threadIdx.x]; sq = sh[8 + threadIdx.x];
#pragma unroll
        for (int o = 4; o; o >>= 1) { sm += __shfl_xor_sync(0xffu, sm, o); sq += __shfl_xor_sync(0xffu, sq, o); }
        if (threadIdx.x == 0) { sh[0] = sm; sh[8] = sq; }
    }
    __syncthreads();
    float mean = sh[0] * (1.f/DD);
    float var  = sh[8] * (1.f/DD) - mean*mean;
    float rs = rsqrtf(var + 1e-5f);
    float4 gg = *(const float4*)(g + d0);
    float4 bb = *(const float4*)(bt + d0);
    float4 ov;
    ov.x = (v.x-mean)*rs*gg.x + bb.x;
    ov.y = (v.y-mean)*rs*gg.y + bb.y;
    ov.z = (v.z-mean)*rs*gg.z + bb.z;
    ov.w = (v.w-mean)*rs*gg.w + bb.w;
    *(float4*)(out + (size_t)t*DD + d0) = ov;
}

// ---------------- router / bookkeeping ------------------------------------
__global__ void zero_cnt_kernel() {
    if (threadIdx.x < EE) g_cnt[threadIdx.x] = 0;
}

__global__ __launch_bounds__(256)
void router_kernel(const float* __restrict__ X, const float* __restrict__ rw,
                   const float* __restrict__ rb)
{
    int warp = (blockIdx.x * blockDim.x + threadIdx.x) >> 5;
    int lane = threadIdx.x & 31;
    if (warp >= TT) return;
    const float* xr = X + (size_t)warp * DD;
    float acc[EE];
#pragma unroll
    for (int e = 0; e < EE; e++) acc[e] = 0.f;
    for (int d = lane; d < DD; d += 32) {
        float xv = xr[d];
        const float* wrow = rw + (size_t)d * EE;
#pragma unroll
        for (int e = 0; e < EE; e++) acc[e] += xv * wrow[e];
    }
#pragma unroll
    for (int e = 0; e < EE; e++)
#pragma unroll
        for (int o = 16; o; o >>= 1) acc[e] += __shfl_xor_sync(~0u, acc[e], o);
    if (lane == 0) {
        float logits[EE], p[EE];
        float mx = -1e30f;
#pragma unroll
        for (int e = 0; e < EE; e++) { logits[e] = acc[e] + rb[e]; mx = fmaxf(mx, logits[e]); }
        float se = 0.f;
#pragma unroll
        for (int e = 0; e < EE; e++) { p[e] = __expf(logits[e] - mx); se += p[e]; }
        float inv = 1.f / se;
#pragma unroll
        for (int e = 0; e < EE; e++) p[e] *= inv;
        int i0 = 0;
#pragma unroll
        for (int e = 1; e < EE; e++) if (p[e] > p[i0]) i0 = e;
        int i1 = (i0 == 0) ? 1 : 0;
#pragma unroll
        for (int e = 0; e < EE; e++) if (e != i0 && p[e] > p[i1]) i1 = e;
        float s = p[i0] + p[i1];
        g_te[warp*2+0] = i0; g_te[warp*2+1] = i1;
        g_tw[warp*2+0] = p[i0] / s; g_tw[warp*2+1] = p[i1] / s;
        atomicAdd(&g_cnt[i0], 1);
        atomicAdd(&g_cnt[i1], 1);
    }
}

__global__ void scan_kernel() {
    if (threadIdx.x == 0) {
        int b = 0;
        for (int e = 0; e < EE; e++) { g_base[e] = b; g_cur[e] = b; b += g_cnt[e]; }
    }
}

__global__ __launch_bounds__(256)
void place_kernel() {
    int t = blockIdx.x * blockDim.x + threadIdx.x;
    if (t >= TT) return;
#pragma unroll
    for (int k = 0; k < TOPK; k++) {
        int e = g_te[t*2+k];
        int pos = atomicAdd(&g_cur[e], 1);
        g_tok[pos] = t;
        g_epos[t*2+k] = pos;
    }
}

// ---------------- launcher -------------------------------------------------
extern "C" void kernel_launch(void* const* d_in, const int* in_sizes, int n_in,
                              void* d_out, int out_size)
{
    const float* tgt   = (const float*)d_in[0];
    const float* mem   = (const float*)d_in[1];
    const float* sa_wq = (const float*)d_in[2];  const float* sa_bq = (const float*)d_in[3];
    const float* sa_wk = (const float*)d_in[4];  const float* sa_bk = (const float*)d_in[5];
    const float* sa_wv = (const float*)d_in[6];  const float* sa_bv = (const float*)d_in[7];
    const float* sa_wo = (const float*)d_in[8];  const float* sa_bo = (const float*)d_in[9];
    const float* ca_wq = (const float*)d_in[10]; const float* ca_bq = (const float*)d_in[11];
    const float* ca_wk = (const float*)d_in[12]; const float* ca_bk = (const float*)d_in[13];
    const float* ca_wv = (const float*)d_in[14]; const float* ca_bv = (const float*)d_in[15];
    const float* ca_wo = (const float*)d_in[16]; const float* ca_bo = (const float*)d_in[17];
    const float* r_w   = (const float*)d_in[18]; const float* r_b   = (const float*)d_in[19];
    const float* e_w1  = (const float*)d_in[20]; const float* e_b1  = (const float*)d_in[21];
    const float* e_w2  = (const float*)d_in[22]; const float* e_b2  = (const float*)d_in[23];
    const float* n1_g  = (const float*)d_in[24]; const float* n1_b  = (const float*)d_in[25];
    const float* n2_g  = (const float*)d_in[26]; const float* n2_b  = (const float*)d_in[27];
    const float* n3_g  = (const float*)d_in[28]; const float* n3_b  = (const float*)d_in[29];
    float* out = (float*)d_out;

    dim3 gproj(DD/BN, TT/BM);          // (8, 64)
    dim3 gproj3(DD/BN, TT/BM, 3);      // fused QKV
    dim3 gattn(SS/64, HH, BB);         // (32, 16, 4)
    dim3 gmoe1(HID/BN, TT/BM, EE);
    dim3 gmoe2(DD/BN,  TT/BM, EE);

    // ---- self-attention block (fused QKV; O-proj folds residual) ----
    sgemm3<<<gproj3, 256>>>(tgt, tgt, tgt,
                            sa_wq, sa_wk, sa_wv,
                            sa_bq, sa_bk, sa_bv,
                            g_q, g_k, g_v, DD, DD);
    attn_kernel<<<gattn, 64>>>(g_q, g_k, g_v, g_att);
    sgemm_r<1><<<gproj, 256>>>(g_att, sa_wo, sa_bo, tgt, g_tmp, DD, DD);
    ln_kernel<<<TT, 256>>>(g_tmp, n1_g, n1_b, g_x1);

    // ---- cross-attention block ----
    sgemm3<<<gproj3, 256>>>(g_x1, mem, mem,
                            ca_wq, ca_wk, ca_wv,
                            ca_bq, ca_bk, ca_bv,
                            g_q, g_k, g_v, DD, DD);
    attn_kernel<<<gattn, 64>>>(g_q, g_k, g_v, g_att);
    sgemm_r<1><<<gproj, 256>>>(g_att, ca_wo, ca_bo, g_x1, g_tmp, DD, DD);
    ln_kernel<<<TT, 256>>>(g_tmp, n2_g, n2_b, g_x2);

    // ---- sparse MoE ----
    zero_cnt_kernel<<<1, 32>>>();
    router_kernel<<<TT/8, 256>>>(g_x2, r_w, r_b);
    scan_kernel<<<1, 32>>>();
    place_kernel<<<TT/256, 256>>>();
    moe_gemm<true,1><<<gmoe1, 256>>>(g_x2,  e_w1, e_b1, g_hid, HID, DD);
    moe_gemm<false,2><<<gmoe2, 256>>>(g_hid, e_w2, e_b2, g_y,  DD,  HID);
    combine_ln_kernel<<<TT, 256>>>(g_x2, g_y, n3_g, n3_b, out);
}